// round 1
// baseline (speedup 1.0000x reference)
#include <cuda_runtime.h>

// ---------------------------------------------------------------------------
// HMPNN layer: two NNConv(sum) meta-steps + sigmoid + concat + Linear + sigmoid
//   msg[e,o] = sum_i xj[e,i] * ( b_msg[i,o] + sum_f ea[e,f] * w_msg[f,i,o] )
//   agg[n]   = segment_sum(msg by dst) + x_indivi[n] @ root + bias
//   out      = sigmoid( concat(sig(agg_a), sig(agg_b)) @ w_lin + b_lin )
// Strategy: pack 2 edges per thread into f32x2 (FFMA2 path on sm_103a).
// ---------------------------------------------------------------------------

#define NMAX 50000

typedef unsigned long long ull;

// scratch accumulators (allocation-free rule: __device__ globals)
__device__ float g_agg[2][NMAX * 16];

__device__ __forceinline__ ull pk2(float x, float y) {
    ull r;
    asm("mov.b64 %0, {%1,%2};" : "=l"(r)
        : "r"(__float_as_uint(x)), "r"(__float_as_uint(y)));
    return r;
}
__device__ __forceinline__ void unpk2(ull a, float& x, float& y) {
    unsigned lo, hi;
    asm("mov.b64 {%0,%1}, %2;" : "=r"(lo), "=r"(hi) : "l"(a));
    x = __uint_as_float(lo);
    y = __uint_as_float(hi);
}
__device__ __forceinline__ ull mul2(ull a, ull b) {
    ull r;
    asm("mul.rn.f32x2 %0, %1, %2;" : "=l"(r) : "l"(a), "l"(b));
    return r;
}
__device__ __forceinline__ ull fma2(ull a, ull b, ull c) {
    ull r;
    asm("fma.rn.f32x2 %0, %1, %2, %3;" : "=l"(r) : "l"(a), "l"(b), "l"(c));
    return r;
}

__device__ __forceinline__ float sigmoidf(float x) {
    return 1.0f / (1.0f + __expf(-x));
}

// ---------------------------------------------------------------------------
// init: agg[step][n][o] = bias[o] + sum_i x_indivi[n,i] * root[i,o]
// ---------------------------------------------------------------------------
__global__ void init_kernel(const float* __restrict__ x_indivi,
                            const float* __restrict__ root_a,
                            const float* __restrict__ bias_a,
                            const float* __restrict__ root_b,
                            const float* __restrict__ bias_b,
                            int N) {
    int n = blockIdx.x * blockDim.x + threadIdx.x;
    if (n >= N) return;

    float x[16];
    const float4* xr = (const float4*)(x_indivi + n * 16);
#pragma unroll
    for (int j = 0; j < 4; ++j) {
        float4 v = xr[j];
        x[4 * j + 0] = v.x; x[4 * j + 1] = v.y;
        x[4 * j + 2] = v.z; x[4 * j + 3] = v.w;
    }

    float sa[16], sb[16];
#pragma unroll
    for (int o = 0; o < 16; ++o) {
        sa[o] = bias_a[o];
        sb[o] = bias_b[o];
    }
#pragma unroll
    for (int i = 0; i < 16; ++i) {
#pragma unroll
        for (int o = 0; o < 16; ++o) {
            sa[o] += x[i] * root_a[i * 16 + o];
            sb[o] += x[i] * root_b[i * 16 + o];
        }
    }
#pragma unroll
    for (int o = 0; o < 16; ++o) {
        g_agg[0][n * 16 + o] = sa[o];
        g_agg[1][n * 16 + o] = sb[o];
    }
}

// ---------------------------------------------------------------------------
// edge: 2 edges per thread, f32x2-packed einsum + atomic scatter
// blockIdx.y selects meta-step (0 = a, 1 = b)
// ---------------------------------------------------------------------------
__global__ __launch_bounds__(128) void edge_kernel(
    const float* __restrict__ xs_a, const float* __restrict__ xs_b,
    const int* __restrict__ ei_a, const int* __restrict__ ei_b,
    const float* __restrict__ eat_a, const float* __restrict__ eat_b,
    const float* __restrict__ wm_a, const float* __restrict__ bm_a,
    const float* __restrict__ wm_b, const float* __restrict__ bm_b,
    int E) {
    const int step = blockIdx.y;
    const float* __restrict__ xs  = step ? xs_b  : xs_a;
    const int*   __restrict__ ei  = step ? ei_b  : ei_a;
    const float* __restrict__ eat = step ? eat_b : eat_a;
    const float* __restrict__ wm  = step ? wm_b  : wm_a;
    const float* __restrict__ bm  = step ? bm_b  : bm_a;

    // w_msg duplicated into both f32x2 lanes; broadcast LDS -> conflict-free
    __shared__ __align__(16) ull w2[4096];   // [f][i][o]
    __shared__ __align__(16) ull b2[256];    // [i][o]
    for (int k = threadIdx.x; k < 4096; k += 128) {
        float v = wm[k];
        w2[k] = pk2(v, v);
    }
    for (int k = threadIdx.x; k < 256; k += 128) {
        float v = bm[k];
        b2[k] = pk2(v, v);
    }
    __syncthreads();

    const int half = (E + 1) >> 1;
    int t = blockIdx.x * 128 + threadIdx.x;
    if (t >= half) return;

    int e0 = t;
    int e1 = t + half;
    bool has1 = (e1 < E);
    if (!has1) e1 = e0;

    // gather source node features for both edges, pack as f32x2
    int s0 = ei[e0];
    int s1 = ei[e1];
    ull xj2[16];
    {
        const float4* xr0 = (const float4*)(xs + s0 * 16);
        const float4* xr1 = (const float4*)(xs + s1 * 16);
#pragma unroll
        for (int j = 0; j < 4; ++j) {
            float4 v0 = xr0[j];
            float4 v1 = xr1[j];
            xj2[4 * j + 0] = pk2(v0.x, v1.x);
            xj2[4 * j + 1] = pk2(v0.y, v1.y);
            xj2[4 * j + 2] = pk2(v0.z, v1.z);
            xj2[4 * j + 3] = pk2(v0.w, v1.w);
        }
    }

    ull acc[16];
    // bias term: acc[o] = sum_i xj[i] * b_msg[i,o]
#pragma unroll
    for (int i = 0; i < 16; ++i) {
        ull p = xj2[i];
        const ulonglong2* br = (const ulonglong2*)(b2 + (i << 4));
        if (i == 0) {
#pragma unroll
            for (int j = 0; j < 8; ++j) {
                ulonglong2 wv = br[j];
                acc[2 * j + 0] = mul2(p, wv.x);
                acc[2 * j + 1] = mul2(p, wv.y);
            }
        } else {
#pragma unroll
            for (int j = 0; j < 8; ++j) {
                ulonglong2 wv = br[j];
                acc[2 * j + 0] = fma2(p, wv.x, acc[2 * j + 0]);
                acc[2 * j + 1] = fma2(p, wv.y, acc[2 * j + 1]);
            }
        }
    }

    // main contraction: f kept as a rolled loop (ea re-read from L1 each iter,
    // keeps registers low and I-footprint small)
    for (int f = 0; f < 16; ++f) {
        ull eaf = pk2(eat[e0 * 16 + f], eat[e1 * 16 + f]);
        const ulonglong2* wf = (const ulonglong2*)(w2 + (f << 8));
#pragma unroll
        for (int i = 0; i < 16; ++i) {
            ull p = mul2(eaf, xj2[i]);
            const ulonglong2* wr = wf + (i << 3);
#pragma unroll
            for (int j = 0; j < 8; ++j) {
                ulonglong2 wv = wr[j];
                acc[2 * j + 0] = fma2(p, wv.x, acc[2 * j + 0]);
                acc[2 * j + 1] = fma2(p, wv.y, acc[2 * j + 1]);
            }
        }
    }

    // scatter-add into per-node accumulators
    int d0 = ei[E + e0];
    int d1 = ei[E + e1];
    float* agg = g_agg[step];
#pragma unroll
    for (int o = 0; o < 16; ++o) {
        float v0, v1;
        unpk2(acc[o], v0, v1);
        atomicAdd(&agg[d0 * 16 + o], v0);
        if (has1) atomicAdd(&agg[d1 * 16 + o], v1);
    }
}

// ---------------------------------------------------------------------------
// final: out[n] = sigmoid( [sig(agg_a[n]), sig(agg_b[n])] @ w_lin + b_lin )
// ---------------------------------------------------------------------------
__global__ void final_kernel(const float* __restrict__ w_lin,
                             const float* __restrict__ b_lin,
                             float* __restrict__ out, int N) {
    __shared__ float wl[32 * 32];
    __shared__ float bl[32];
    for (int k = threadIdx.x; k < 1024; k += blockDim.x) wl[k] = w_lin[k];
    if (threadIdx.x < 32) bl[threadIdx.x] = b_lin[threadIdx.x];
    __syncthreads();

    int n = blockIdx.x * blockDim.x + threadIdx.x;
    if (n >= N) return;

    float s[32];
#pragma unroll
    for (int k = 0; k < 16; ++k) s[k]      = sigmoidf(g_agg[0][n * 16 + k]);
#pragma unroll
    for (int k = 0; k < 16; ++k) s[16 + k] = sigmoidf(g_agg[1][n * 16 + k]);

#pragma unroll
    for (int o = 0; o < 32; ++o) {
        float v = bl[o];
#pragma unroll
        for (int k = 0; k < 32; ++k) v += s[k] * wl[k * 32 + o];
        out[n * 32 + o] = sigmoidf(v);
    }
}

// ---------------------------------------------------------------------------
extern "C" void kernel_launch(void* const* d_in, const int* in_sizes, int n_in,
                              void* d_out, int out_size) {
    const float* x_indivi = (const float*)d_in[0];
    const float* x_src_a  = (const float*)d_in[1];
    const float* x_src_b  = (const float*)d_in[2];
    const int*   ei_a     = (const int*)d_in[3];
    const int*   ei_b     = (const int*)d_in[4];
    const float* ea_a     = (const float*)d_in[5];
    const float* ea_b     = (const float*)d_in[6];
    const float* wm_a     = (const float*)d_in[7];
    const float* bm_a     = (const float*)d_in[8];
    const float* root_a   = (const float*)d_in[9];
    const float* bias_a   = (const float*)d_in[10];
    const float* wm_b     = (const float*)d_in[11];
    const float* bm_b     = (const float*)d_in[12];
    const float* root_b   = (const float*)d_in[13];
    const float* bias_b   = (const float*)d_in[14];
    const float* w_lin    = (const float*)d_in[15];
    const float* b_lin    = (const float*)d_in[16];
    float* out = (float*)d_out;

    int N = in_sizes[0] / 16;
    int E = in_sizes[3] / 2;   // edge_index is [2, E]
    int half = (E + 1) >> 1;

    init_kernel<<<(N + 127) / 128, 128>>>(x_indivi, root_a, bias_a,
                                          root_b, bias_b, N);

    dim3 egrid((half + 127) / 128, 2);
    edge_kernel<<<egrid, 128>>>(x_src_a, x_src_b, ei_a, ei_b, ea_a, ea_b,
                                wm_a, bm_a, wm_b, bm_b, E);

    final_kernel<<<(N + 127) / 128, 128>>>(w_lin, b_lin, out, N);
}

// round 2
// speedup vs baseline: 1.2392x; 1.2392x over previous
#include <cuda_runtime.h>

// ---------------------------------------------------------------------------
// HMPNN layer: two NNConv(sum) meta-steps + sigmoid + concat + Linear + sigmoid
//   msg[e,o] = sum_i xj[e,i] * ( b_msg[i,o] + sum_f ea[e,f] * w_msg[f,i,o] )
//   agg[n]   = segment_sum(msg by dst) + x_indivi[n] @ root + bias
//   out      = sigmoid( concat(sig(agg_a), sig(agg_b)) @ w_lin + b_lin )
// R2: 4 edges/thread (2x f32x2), bias folded as 17th f-block, red.v4 scatter,
//     per-step edge launches.
// ---------------------------------------------------------------------------

#define NMAX 50000

typedef unsigned long long ull;

__device__ float g_agg[2][NMAX * 16];

__device__ __forceinline__ ull pk2(float x, float y) {
    ull r;
    asm("mov.b64 %0, {%1,%2};" : "=l"(r)
        : "r"(__float_as_uint(x)), "r"(__float_as_uint(y)));
    return r;
}
__device__ __forceinline__ void unpk2(ull a, float& x, float& y) {
    unsigned lo, hi;
    asm("mov.b64 {%0,%1}, %2;" : "=r"(lo), "=r"(hi) : "l"(a));
    x = __uint_as_float(lo);
    y = __uint_as_float(hi);
}
__device__ __forceinline__ ull mul2(ull a, ull b) {
    ull r;
    asm("mul.rn.f32x2 %0, %1, %2;" : "=l"(r) : "l"(a), "l"(b));
    return r;
}
__device__ __forceinline__ ull fma2(ull a, ull b, ull c) {
    ull r;
    asm("fma.rn.f32x2 %0, %1, %2, %3;" : "=l"(r) : "l"(a), "l"(b), "l"(c));
    return r;
}
__device__ __forceinline__ void red4(float* p, float a, float b, float c, float d) {
    asm volatile("red.global.add.v4.f32 [%0], {%1,%2,%3,%4};"
                 :: "l"(p), "f"(a), "f"(b), "f"(c), "f"(d) : "memory");
}

__device__ __forceinline__ float sigmoidf(float x) {
    return 1.0f / (1.0f + __expf(-x));
}

// ---------------------------------------------------------------------------
// init: agg[step][n][o] = bias[o] + sum_i x_indivi[n,i] * root[i,o]
// ---------------------------------------------------------------------------
__global__ void init_kernel(const float* __restrict__ x_indivi,
                            const float* __restrict__ root_a,
                            const float* __restrict__ bias_a,
                            const float* __restrict__ root_b,
                            const float* __restrict__ bias_b,
                            int N) {
    int n = blockIdx.x * blockDim.x + threadIdx.x;
    if (n >= N) return;

    float x[16];
    const float4* xr = (const float4*)(x_indivi + n * 16);
#pragma unroll
    for (int j = 0; j < 4; ++j) {
        float4 v = xr[j];
        x[4 * j + 0] = v.x; x[4 * j + 1] = v.y;
        x[4 * j + 2] = v.z; x[4 * j + 3] = v.w;
    }

    float sa[16], sb[16];
#pragma unroll
    for (int o = 0; o < 16; ++o) {
        sa[o] = bias_a[o];
        sb[o] = bias_b[o];
    }
#pragma unroll
    for (int i = 0; i < 16; ++i) {
#pragma unroll
        for (int o = 0; o < 16; ++o) {
            sa[o] += x[i] * root_a[i * 16 + o];
            sb[o] += x[i] * root_b[i * 16 + o];
        }
    }
#pragma unroll
    for (int o = 0; o < 16; ++o) {
        g_agg[0][n * 16 + o] = sa[o];
        g_agg[1][n * 16 + o] = sb[o];
    }
}

// ---------------------------------------------------------------------------
// edge: 4 edges per thread as two f32x2 pairs; each SMEM weight load feeds
// 4 fma2 (64 MACs). Weight table w2: [f=0..16][i][o], block f=16 = b_msg.
// ---------------------------------------------------------------------------
__global__ __launch_bounds__(256) void edge_kernel(
    const float* __restrict__ xs,
    const int* __restrict__ ei,
    const float* __restrict__ eat,
    const float* __restrict__ wm,
    const float* __restrict__ bm,
    float* __restrict__ agg,
    int E) {
    __shared__ __align__(16) ull w2[17 * 256];
    for (int k = threadIdx.x; k < 4096; k += 256) {
        float v = wm[k];
        w2[k] = pk2(v, v);
    }
    {
        int k = threadIdx.x;
        if (k < 256) {
            float v = bm[k];
            w2[4096 + k] = pk2(v, v);
        }
    }
    __syncthreads();

    const int q = (E + 3) >> 2;
    int t = blockIdx.x * 256 + threadIdx.x;
    if (t >= q) return;

    int e0 = t, e1 = t + q, e2 = t + 2 * q, e3 = t + 3 * q;
    bool h1 = e1 < E, h2 = e2 < E, h3 = e3 < E;
    if (!h1) e1 = e0;
    if (!h2) e2 = e0;
    if (!h3) e3 = e0;

    int s0 = ei[e0], s1 = ei[e1], s2 = ei[e2], s3 = ei[e3];

    // gather + pack source features: pair A = (e0,e1), pair B = (e2,e3)
    ull xjA[16], xjB[16];
    {
        const float4* x0 = (const float4*)(xs + s0 * 16);
        const float4* x1 = (const float4*)(xs + s1 * 16);
        const float4* x2 = (const float4*)(xs + s2 * 16);
        const float4* x3 = (const float4*)(xs + s3 * 16);
#pragma unroll
        for (int j = 0; j < 4; ++j) {
            float4 a = x0[j], b = x1[j], c = x2[j], d = x3[j];
            xjA[4 * j + 0] = pk2(a.x, b.x); xjB[4 * j + 0] = pk2(c.x, d.x);
            xjA[4 * j + 1] = pk2(a.y, b.y); xjB[4 * j + 1] = pk2(c.y, d.y);
            xjA[4 * j + 2] = pk2(a.z, b.z); xjB[4 * j + 2] = pk2(c.z, d.z);
            xjA[4 * j + 3] = pk2(a.w, b.w); xjB[4 * j + 3] = pk2(c.w, d.w);
        }
    }

    ull accA[16], accB[16];

    // bias block (f=16): acc[o] = sum_i xj[i] * b_msg[i,o]
    {
        const ulonglong2* wb = (const ulonglong2*)(w2 + 4096);
#pragma unroll
        for (int i = 0; i < 16; ++i) {
            ull pA = xjA[i];
            ull pB = xjB[i];
            const ulonglong2* wr = wb + (i << 3);
            if (i == 0) {
#pragma unroll
                for (int j = 0; j < 8; ++j) {
                    ulonglong2 wv = wr[j];
                    accA[2 * j + 0] = mul2(pA, wv.x);
                    accB[2 * j + 0] = mul2(pB, wv.x);
                    accA[2 * j + 1] = mul2(pA, wv.y);
                    accB[2 * j + 1] = mul2(pB, wv.y);
                }
            } else {
#pragma unroll
                for (int j = 0; j < 8; ++j) {
                    ulonglong2 wv = wr[j];
                    accA[2 * j + 0] = fma2(pA, wv.x, accA[2 * j + 0]);
                    accB[2 * j + 0] = fma2(pB, wv.x, accB[2 * j + 0]);
                    accA[2 * j + 1] = fma2(pA, wv.y, accA[2 * j + 1]);
                    accB[2 * j + 1] = fma2(pB, wv.y, accB[2 * j + 1]);
                }
            }
        }
    }

    // main contraction
    for (int f = 0; f < 16; ++f) {
        ull eaA = pk2(eat[e0 * 16 + f], eat[e1 * 16 + f]);
        ull eaB = pk2(eat[e2 * 16 + f], eat[e3 * 16 + f]);
        const ulonglong2* wf = (const ulonglong2*)(w2 + (f << 8));
#pragma unroll
        for (int i = 0; i < 16; ++i) {
            ull pA = mul2(eaA, xjA[i]);
            ull pB = mul2(eaB, xjB[i]);
            const ulonglong2* wr = wf + (i << 3);
#pragma unroll
            for (int j = 0; j < 8; ++j) {
                ulonglong2 wv = wr[j];
                accA[2 * j + 0] = fma2(pA, wv.x, accA[2 * j + 0]);
                accB[2 * j + 0] = fma2(pB, wv.x, accB[2 * j + 0]);
                accA[2 * j + 1] = fma2(pA, wv.y, accA[2 * j + 1]);
                accB[2 * j + 1] = fma2(pB, wv.y, accB[2 * j + 1]);
            }
        }
    }

    // scatter: 4 x red.global.add.v4.f32 per edge
    int d0 = ei[E + e0], d1 = ei[E + e1], d2 = ei[E + e2], d3 = ei[E + e3];
    float v0[16], v1[16], v2[16], v3[16];
#pragma unroll
    for (int o = 0; o < 16; ++o) {
        unpk2(accA[o], v0[o], v1[o]);
        unpk2(accB[o], v2[o], v3[o]);
    }
#pragma unroll
    for (int j = 0; j < 4; ++j)
        red4(&agg[d0 * 16 + 4 * j], v0[4 * j], v0[4 * j + 1], v0[4 * j + 2], v0[4 * j + 3]);
    if (h1)
#pragma unroll
        for (int j = 0; j < 4; ++j)
            red4(&agg[d1 * 16 + 4 * j], v1[4 * j], v1[4 * j + 1], v1[4 * j + 2], v1[4 * j + 3]);
    if (h2)
#pragma unroll
        for (int j = 0; j < 4; ++j)
            red4(&agg[d2 * 16 + 4 * j], v2[4 * j], v2[4 * j + 1], v2[4 * j + 2], v2[4 * j + 3]);
    if (h3)
#pragma unroll
        for (int j = 0; j < 4; ++j)
            red4(&agg[d3 * 16 + 4 * j], v3[4 * j], v3[4 * j + 1], v3[4 * j + 2], v3[4 * j + 3]);
}

// ---------------------------------------------------------------------------
// final: out[n] = sigmoid( [sig(agg_a[n]), sig(agg_b[n])] @ w_lin + b_lin )
// ---------------------------------------------------------------------------
__global__ void final_kernel(const float* __restrict__ w_lin,
                             const float* __restrict__ b_lin,
                             float* __restrict__ out, int N) {
    __shared__ float wl[32 * 32];
    __shared__ float bl[32];
    for (int k = threadIdx.x; k < 1024; k += blockDim.x) wl[k] = w_lin[k];
    if (threadIdx.x < 32) bl[threadIdx.x] = b_lin[threadIdx.x];
    __syncthreads();

    int n = blockIdx.x * blockDim.x + threadIdx.x;
    if (n >= N) return;

    float s[32];
#pragma unroll
    for (int k = 0; k < 16; ++k) s[k]      = sigmoidf(g_agg[0][n * 16 + k]);
#pragma unroll
    for (int k = 0; k < 16; ++k) s[16 + k] = sigmoidf(g_agg[1][n * 16 + k]);

#pragma unroll
    for (int o = 0; o < 32; ++o) {
        float v = bl[o];
#pragma unroll
        for (int k = 0; k < 32; ++k) v += s[k] * wl[k * 32 + o];
        out[n * 32 + o] = sigmoidf(v);
    }
}

// ---------------------------------------------------------------------------
extern "C" void kernel_launch(void* const* d_in, const int* in_sizes, int n_in,
                              void* d_out, int out_size) {
    const float* x_indivi = (const float*)d_in[0];
    const float* x_src_a  = (const float*)d_in[1];
    const float* x_src_b  = (const float*)d_in[2];
    const int*   ei_a     = (const int*)d_in[3];
    const int*   ei_b     = (const int*)d_in[4];
    const float* ea_a     = (const float*)d_in[5];
    const float* ea_b     = (const float*)d_in[6];
    const float* wm_a     = (const float*)d_in[7];
    const float* bm_a     = (const float*)d_in[8];
    const float* root_a   = (const float*)d_in[9];
    const float* bias_a   = (const float*)d_in[10];
    const float* wm_b     = (const float*)d_in[11];
    const float* bm_b     = (const float*)d_in[12];
    const float* root_b   = (const float*)d_in[13];
    const float* bias_b   = (const float*)d_in[14];
    const float* w_lin    = (const float*)d_in[15];
    const float* b_lin    = (const float*)d_in[16];
    float* out = (float*)d_out;

    int N = in_sizes[0] / 16;
    int E = in_sizes[3] / 2;   // edge_index is [2, E]
    int q = (E + 3) >> 2;

    float* agg_a;
    float* agg_b;
    cudaGetSymbolAddress((void**)&agg_a, g_agg);
    agg_b = agg_a + NMAX * 16;

    init_kernel<<<(N + 127) / 128, 128>>>(x_indivi, root_a, bias_a,
                                          root_b, bias_b, N);

    int eblocks = (q + 255) / 256;
    edge_kernel<<<eblocks, 256>>>(x_src_a, ei_a, ea_a, wm_a, bm_a, agg_a, E);
    edge_kernel<<<eblocks, 256>>>(x_src_b, ei_b, ea_b, wm_b, bm_b, agg_b, E);

    final_kernel<<<(N + 127) / 128, 128>>>(w_lin, b_lin, out, N);
}

// round 3
// speedup vs baseline: 2.8370x; 2.2893x over previous
#include <cuda_runtime.h>

// ---------------------------------------------------------------------------
// HMPNN layer, R3: algebraic refactor.
//   U[n,f,o] = sum_i x_src[n,i] * w_msg[f,i,o]   (f=16 block holds b_msg term)
//   msg[e,o] = sum_{f<=16} ea'[e,f] * U[src_e,f,o]   (ea'[16]=1)
//   agg[n]   = segment_sum(msg) + x_indivi @ root + bias
//   out      = sigmoid( concat(sig(agg_a), sig(agg_b)) @ w_lin + b_lin )
// Edge phase: 272 MAC/edge + 1088B L2 gather (vs 4352 MAC before).
// ---------------------------------------------------------------------------

#define NMAX 50000
#define UROW 272              // 17 blocks * 16 outputs

__device__ float g_agg[2][NMAX * 16];
__device__ float g_U[2][NMAX * UROW];

__device__ __forceinline__ void red4(float* p, float a, float b, float c, float d) {
    asm volatile("red.global.add.v4.f32 [%0], {%1,%2,%3,%4};"
                 :: "l"(p), "f"(a), "f"(b), "f"(c), "f"(d) : "memory");
}

__device__ __forceinline__ float sigmoidf(float x) {
    return 1.0f / (1.0f + __expf(-x));
}

// ---------------------------------------------------------------------------
// prep: role 0 -> agg init (bias + x_indivi@root), roles 1/2 -> U tables
// ---------------------------------------------------------------------------
__global__ __launch_bounds__(128) void prep_kernel(
    const float* __restrict__ x_indivi,
    const float* __restrict__ xs_a, const float* __restrict__ xs_b,
    const float* __restrict__ root_a, const float* __restrict__ bias_a,
    const float* __restrict__ root_b, const float* __restrict__ bias_b,
    const float* __restrict__ wm_a, const float* __restrict__ bm_a,
    const float* __restrict__ wm_b, const float* __restrict__ bm_b,
    int N) {
    const int role = blockIdx.y;
    const int n = blockIdx.x * 128 + threadIdx.x;

    if (role == 0) {
        if (n >= N) return;
        float x[16];
        const float4* xr = (const float4*)(x_indivi + n * 16);
#pragma unroll
        for (int j = 0; j < 4; ++j) {
            float4 v = xr[j];
            x[4 * j + 0] = v.x; x[4 * j + 1] = v.y;
            x[4 * j + 2] = v.z; x[4 * j + 3] = v.w;
        }
        float sa[16], sb[16];
#pragma unroll
        for (int o = 0; o < 16; ++o) { sa[o] = bias_a[o]; sb[o] = bias_b[o]; }
#pragma unroll
        for (int i = 0; i < 16; ++i) {
#pragma unroll
            for (int o = 0; o < 16; ++o) {
                sa[o] += x[i] * root_a[i * 16 + o];
                sb[o] += x[i] * root_b[i * 16 + o];
            }
        }
#pragma unroll
        for (int o = 0; o < 16; ++o) {
            g_agg[0][n * 16 + o] = sa[o];
            g_agg[1][n * 16 + o] = sb[o];
        }
        return;
    }

    // roles 1,2: build U table for one meta-step
    const float* __restrict__ xs = (role == 1) ? xs_a : xs_b;
    const float* __restrict__ wm = (role == 1) ? wm_a : wm_b;
    const float* __restrict__ bm = (role == 1) ? bm_a : bm_b;
    float* __restrict__ U = g_U[role - 1];

    __shared__ float Ws[17 * 256];     // [f][i][o], f=16 holds b_msg
    for (int k = threadIdx.x; k < 4096; k += 128) Ws[k] = wm[k];
    for (int k = threadIdx.x; k < 256; k += 128) Ws[4096 + k] = bm[k];
    __syncthreads();

    if (n >= N) return;

    float x[16];
    const float4* xr = (const float4*)(xs + n * 16);
#pragma unroll
    for (int j = 0; j < 4; ++j) {
        float4 v = xr[j];
        x[4 * j + 0] = v.x; x[4 * j + 1] = v.y;
        x[4 * j + 2] = v.z; x[4 * j + 3] = v.w;
    }

    float4* Urow = (float4*)(U + n * UROW);
#pragma unroll 1
    for (int f = 0; f < 17; ++f) {
        const float* Wf = Ws + f * 256;
        float acc[16];
#pragma unroll
        for (int o = 0; o < 16; ++o) acc[o] = 0.0f;
#pragma unroll
        for (int i = 0; i < 16; ++i) {
            float xi = x[i];
            const float4* wr = (const float4*)(Wf + i * 16);
#pragma unroll
            for (int j = 0; j < 4; ++j) {
                float4 w = wr[j];
                acc[4 * j + 0] += xi * w.x;
                acc[4 * j + 1] += xi * w.y;
                acc[4 * j + 2] += xi * w.z;
                acc[4 * j + 3] += xi * w.w;
            }
        }
#pragma unroll
        for (int j = 0; j < 4; ++j)
            Urow[f * 4 + j] = make_float4(acc[4 * j], acc[4 * j + 1],
                                          acc[4 * j + 2], acc[4 * j + 3]);
    }
}

// ---------------------------------------------------------------------------
// edge: 4 lanes per edge; lane l owns output block 4l..4l+3.
//   acc4 = U[s][f=16] (bias block) + sum_r ea[e][r] * U[s][r]
//   red.global.add.v4 into agg[dst]
// ---------------------------------------------------------------------------
__global__ __launch_bounds__(256) void edge_kernel(
    const int* __restrict__ ei,
    const float* __restrict__ eat,
    const float* __restrict__ U,
    float* __restrict__ agg,
    int E) {
    int t = blockIdx.x * 256 + threadIdx.x;
    int e = t >> 2;
    int l = t & 3;
    if (e >= E) return;

    int s = __ldg(ei + e);
    int d = __ldg(ei + E + e);

    const float4* __restrict__ Ur = (const float4*)(U + s * UROW);
    const float4* __restrict__ ear = (const float4*)(eat + e * 16);

    // preload all 16 edge-attr values (per-quad broadcast loads, L1-hot)
    float4 ea0 = __ldg(ear + 0);
    float4 ea1 = __ldg(ear + 1);
    float4 ea2 = __ldg(ear + 2);
    float4 ea3 = __ldg(ear + 3);
    float ea[16] = {ea0.x, ea0.y, ea0.z, ea0.w,
                    ea1.x, ea1.y, ea1.z, ea1.w,
                    ea2.x, ea2.y, ea2.z, ea2.w,
                    ea3.x, ea3.y, ea3.z, ea3.w};

    float4 acc = __ldg(Ur + 64 + l);   // bias block (f=16)
#pragma unroll
    for (int r = 0; r < 16; ++r) {
        float4 u = __ldg(Ur + r * 4 + l);
        float er = ea[r];
        acc.x += er * u.x;
        acc.y += er * u.y;
        acc.z += er * u.z;
        acc.w += er * u.w;
    }

    red4(&agg[d * 16 + 4 * l], acc.x, acc.y, acc.z, acc.w);
}

// ---------------------------------------------------------------------------
// final: out[n] = sigmoid( [sig(agg_a[n]), sig(agg_b[n])] @ w_lin + b_lin )
// ---------------------------------------------------------------------------
__global__ void final_kernel(const float* __restrict__ w_lin,
                             const float* __restrict__ b_lin,
                             float* __restrict__ out, int N) {
    __shared__ float wl[32 * 32];
    __shared__ float bl[32];
    for (int k = threadIdx.x; k < 1024; k += blockDim.x) wl[k] = w_lin[k];
    if (threadIdx.x < 32) bl[threadIdx.x] = b_lin[threadIdx.x];
    __syncthreads();

    int n = blockIdx.x * blockDim.x + threadIdx.x;
    if (n >= N) return;

    float s[32];
#pragma unroll
    for (int k = 0; k < 16; ++k) s[k]      = sigmoidf(g_agg[0][n * 16 + k]);
#pragma unroll
    for (int k = 0; k < 16; ++k) s[16 + k] = sigmoidf(g_agg[1][n * 16 + k]);

#pragma unroll
    for (int o = 0; o < 32; ++o) {
        float v = bl[o];
#pragma unroll
        for (int k = 0; k < 32; ++k) v += s[k] * wl[k * 32 + o];
        out[n * 32 + o] = sigmoidf(v);
    }
}

// ---------------------------------------------------------------------------
extern "C" void kernel_launch(void* const* d_in, const int* in_sizes, int n_in,
                              void* d_out, int out_size) {
    const float* x_indivi = (const float*)d_in[0];
    const float* x_src_a  = (const float*)d_in[1];
    const float* x_src_b  = (const float*)d_in[2];
    const int*   ei_a     = (const int*)d_in[3];
    const int*   ei_b     = (const int*)d_in[4];
    const float* ea_a     = (const float*)d_in[5];
    const float* ea_b     = (const float*)d_in[6];
    const float* wm_a     = (const float*)d_in[7];
    const float* bm_a     = (const float*)d_in[8];
    const float* root_a   = (const float*)d_in[9];
    const float* bias_a   = (const float*)d_in[10];
    const float* wm_b     = (const float*)d_in[11];
    const float* bm_b     = (const float*)d_in[12];
    const float* root_b   = (const float*)d_in[13];
    const float* bias_b   = (const float*)d_in[14];
    const float* w_lin    = (const float*)d_in[15];
    const float* b_lin    = (const float*)d_in[16];
    float* out = (float*)d_out;

    int N = in_sizes[0] / 16;
    int E = in_sizes[3] / 2;   // edge_index is [2, E]

    float* agg_base;
    float* U_base;
    cudaGetSymbolAddress((void**)&agg_base, g_agg);
    cudaGetSymbolAddress((void**)&U_base, g_U);
    float* agg_a = agg_base;
    float* agg_b = agg_base + NMAX * 16;
    float* U_a = U_base;
    float* U_b = U_base + NMAX * UROW;

    dim3 pgrid((N + 127) / 128, 3);
    prep_kernel<<<pgrid, 128>>>(x_indivi, x_src_a, x_src_b,
                                root_a, bias_a, root_b, bias_b,
                                wm_a, bm_a, wm_b, bm_b, N);

    int eblocks = (E * 4 + 255) / 256;
    edge_kernel<<<eblocks, 256>>>(ei_a, ea_a, U_a, agg_a, E);
    edge_kernel<<<eblocks, 256>>>(ei_b, ea_b, U_b, agg_b, E);

    final_kernel<<<(N + 127) / 128, 128>>>(w_lin, b_lin, out, N);
}

// round 4
// speedup vs baseline: 3.1878x; 1.1237x over previous
#include <cuda_runtime.h>
#include <cuda_fp16.h>

// ---------------------------------------------------------------------------
// HMPNN layer, R4: U-table factorization + fp16 U gather.
//   U[n,f,o] = sum_i x_src[n,i] * w_msg[f,i,o]   (f=16 block holds xj@b_msg)
//   msg[e,o] = U[src,16,o] + sum_f ea[e,f] * U[src,f,o]
//   agg[n]   = segment_sum(msg) + x_indivi @ root + bias
//   out      = sigmoid( concat(sig(agg_a), sig(agg_b)) @ w_lin + b_lin )
// U stored fp16 (544 B/edge gathered from L2), accumulation fp32.
// ---------------------------------------------------------------------------

#define NMAX 50000
#define UROW 272              // 17 f-blocks * 16 outputs

__device__ float g_agg[2][NMAX * 16];
__device__ __half g_U[2][NMAX * UROW];

__device__ __forceinline__ void red4(float* p, float a, float b, float c, float d) {
    asm volatile("red.global.add.v4.f32 [%0], {%1,%2,%3,%4};"
                 :: "l"(p), "f"(a), "f"(b), "f"(c), "f"(d) : "memory");
}

__device__ __forceinline__ float sigmoidf(float x) {
    return 1.0f / (1.0f + __expf(-x));
}

// ---------------------------------------------------------------------------
// prep: role 0 -> agg init (bias + x_indivi@root), roles 1/2 -> fp16 U tables
// ---------------------------------------------------------------------------
__global__ __launch_bounds__(128) void prep_kernel(
    const float* __restrict__ x_indivi,
    const float* __restrict__ xs_a, const float* __restrict__ xs_b,
    const float* __restrict__ root_a, const float* __restrict__ bias_a,
    const float* __restrict__ root_b, const float* __restrict__ bias_b,
    const float* __restrict__ wm_a, const float* __restrict__ bm_a,
    const float* __restrict__ wm_b, const float* __restrict__ bm_b,
    int N) {
    const int role = blockIdx.y;
    const int n = blockIdx.x * 128 + threadIdx.x;

    if (role == 0) {
        if (n >= N) return;
        float x[16];
        const float4* xr = (const float4*)(x_indivi + n * 16);
#pragma unroll
        for (int j = 0; j < 4; ++j) {
            float4 v = xr[j];
            x[4 * j + 0] = v.x; x[4 * j + 1] = v.y;
            x[4 * j + 2] = v.z; x[4 * j + 3] = v.w;
        }
        float sa[16], sb[16];
#pragma unroll
        for (int o = 0; o < 16; ++o) { sa[o] = bias_a[o]; sb[o] = bias_b[o]; }
#pragma unroll
        for (int i = 0; i < 16; ++i) {
#pragma unroll
            for (int o = 0; o < 16; ++o) {
                sa[o] += x[i] * root_a[i * 16 + o];
                sb[o] += x[i] * root_b[i * 16 + o];
            }
        }
#pragma unroll
        for (int o = 0; o < 16; ++o) {
            g_agg[0][n * 16 + o] = sa[o];
            g_agg[1][n * 16 + o] = sb[o];
        }
        return;
    }

    // roles 1,2: build U table (fp16) for one meta-step
    const float* __restrict__ xs = (role == 1) ? xs_a : xs_b;
    const float* __restrict__ wm = (role == 1) ? wm_a : wm_b;
    const float* __restrict__ bm = (role == 1) ? bm_a : bm_b;
    __half* __restrict__ U = g_U[role - 1];

    __shared__ float Ws[17 * 256];     // [f][i][o], f=16 holds b_msg
    for (int k = threadIdx.x; k < 4096; k += 128) Ws[k] = wm[k];
    for (int k = threadIdx.x; k < 256; k += 128) Ws[4096 + k] = bm[k];
    __syncthreads();

    if (n >= N) return;

    float x[16];
    const float4* xr = (const float4*)(xs + n * 16);
#pragma unroll
    for (int j = 0; j < 4; ++j) {
        float4 v = xr[j];
        x[4 * j + 0] = v.x; x[4 * j + 1] = v.y;
        x[4 * j + 2] = v.z; x[4 * j + 3] = v.w;
    }

    __half* Urow = U + n * UROW;
#pragma unroll 1
    for (int f = 0; f < 17; ++f) {
        const float* Wf = Ws + f * 256;
        float acc[16];
#pragma unroll
        for (int o = 0; o < 16; ++o) acc[o] = 0.0f;
#pragma unroll
        for (int i = 0; i < 16; ++i) {
            float xi = x[i];
            const float4* wr = (const float4*)(Wf + i * 16);
#pragma unroll
            for (int j = 0; j < 4; ++j) {
                float4 w = wr[j];
                acc[4 * j + 0] += xi * w.x;
                acc[4 * j + 1] += xi * w.y;
                acc[4 * j + 2] += xi * w.z;
                acc[4 * j + 3] += xi * w.w;
            }
        }
        __half2 h[8];
#pragma unroll
        for (int j = 0; j < 8; ++j)
            h[j] = __floats2half2_rn(acc[2 * j], acc[2 * j + 1]);
        uint4* dst = (uint4*)(Urow + f * 16);
        dst[0] = *(const uint4*)&h[0];
        dst[1] = *(const uint4*)&h[4];
    }
}

// ---------------------------------------------------------------------------
// edge: 2 lanes per edge; lane l owns outputs 8l..8l+7 (one LDG.128 per f).
// ---------------------------------------------------------------------------
__global__ __launch_bounds__(256) void edge_kernel(
    const int* __restrict__ ei,
    const float* __restrict__ eat,
    const __half* __restrict__ U,
    float* __restrict__ agg,
    int E) {
    int t = blockIdx.x * 256 + threadIdx.x;
    int e = t >> 1;
    int l = t & 1;
    if (e >= E) return;

    int s = __ldg(ei + e);
    int d = __ldg(ei + E + e);

    const uint4* __restrict__ Ur = (const uint4*)(U + s * UROW) + l;  // 16B units
    const float4* __restrict__ ear = (const float4*)(eat + e * 16);

    float4 ea0 = __ldg(ear + 0);
    float4 ea1 = __ldg(ear + 1);
    float4 ea2 = __ldg(ear + 2);
    float4 ea3 = __ldg(ear + 3);
    float ea[16] = {ea0.x, ea0.y, ea0.z, ea0.w,
                    ea1.x, ea1.y, ea1.z, ea1.w,
                    ea2.x, ea2.y, ea2.z, ea2.w,
                    ea3.x, ea3.y, ea3.z, ea3.w};

    // bias block f=16 at uint4 index 32
    float4 accL, accH;
    {
        uint4 u = __ldg(Ur + 32);
        const __half2* h = (const __half2*)&u;
        float2 f0 = __half22float2(h[0]);
        float2 f1 = __half22float2(h[1]);
        float2 f2 = __half22float2(h[2]);
        float2 f3 = __half22float2(h[3]);
        accL = make_float4(f0.x, f0.y, f1.x, f1.y);
        accH = make_float4(f2.x, f2.y, f3.x, f3.y);
    }

#pragma unroll
    for (int r = 0; r < 16; ++r) {
        uint4 u = __ldg(Ur + r * 2);
        float er = ea[r];
        const __half2* h = (const __half2*)&u;
        float2 f0 = __half22float2(h[0]);
        float2 f1 = __half22float2(h[1]);
        float2 f2 = __half22float2(h[2]);
        float2 f3 = __half22float2(h[3]);
        accL.x += er * f0.x; accL.y += er * f0.y;
        accL.z += er * f1.x; accL.w += er * f1.y;
        accH.x += er * f2.x; accH.y += er * f2.y;
        accH.z += er * f3.x; accH.w += er * f3.y;
    }

    float* base = &agg[d * 16 + 8 * l];
    red4(base,     accL.x, accL.y, accL.z, accL.w);
    red4(base + 4, accH.x, accH.y, accH.z, accH.w);
}

// ---------------------------------------------------------------------------
// final: out[n] = sigmoid( [sig(agg_a[n]), sig(agg_b[n])] @ w_lin + b_lin )
// vectorized: float4 weight loads, float4 agg loads, float4 stores.
// ---------------------------------------------------------------------------
__global__ __launch_bounds__(256) void final_kernel(
    const float* __restrict__ w_lin,
    const float* __restrict__ b_lin,
    float* __restrict__ out, int N) {
    __shared__ __align__(16) float wl[32 * 32];
    __shared__ float bl[32];
    for (int k = threadIdx.x; k < 1024; k += 256) wl[k] = w_lin[k];
    if (threadIdx.x < 32) bl[threadIdx.x] = b_lin[threadIdx.x];
    __syncthreads();

    int n = blockIdx.x * 256 + threadIdx.x;
    if (n >= N) return;

    float s[32];
    {
        const float4* ga = (const float4*)(&g_agg[0][n * 16]);
        const float4* gb = (const float4*)(&g_agg[1][n * 16]);
#pragma unroll
        for (int j = 0; j < 4; ++j) {
            float4 va = ga[j];
            s[4 * j + 0] = sigmoidf(va.x); s[4 * j + 1] = sigmoidf(va.y);
            s[4 * j + 2] = sigmoidf(va.z); s[4 * j + 3] = sigmoidf(va.w);
        }
#pragma unroll
        for (int j = 0; j < 4; ++j) {
            float4 vb = gb[j];
            s[16 + 4 * j + 0] = sigmoidf(vb.x); s[16 + 4 * j + 1] = sigmoidf(vb.y);
            s[16 + 4 * j + 2] = sigmoidf(vb.z); s[16 + 4 * j + 3] = sigmoidf(vb.w);
        }
    }

    float4 acc[8];
#pragma unroll
    for (int j = 0; j < 8; ++j) {
        acc[j] = make_float4(bl[4 * j], bl[4 * j + 1], bl[4 * j + 2], bl[4 * j + 3]);
    }
#pragma unroll
    for (int k = 0; k < 32; ++k) {
        float sk = s[k];
        const float4* w4 = (const float4*)(wl + k * 32);
#pragma unroll
        for (int j = 0; j < 8; ++j) {
            float4 w = w4[j];
            acc[j].x += sk * w.x;
            acc[j].y += sk * w.y;
            acc[j].z += sk * w.z;
            acc[j].w += sk * w.w;
        }
    }

    float4* o4 = (float4*)(out + n * 32);
#pragma unroll
    for (int j = 0; j < 8; ++j) {
        o4[j] = make_float4(sigmoidf(acc[j].x), sigmoidf(acc[j].y),
                            sigmoidf(acc[j].z), sigmoidf(acc[j].w));
    }
}

// ---------------------------------------------------------------------------
extern "C" void kernel_launch(void* const* d_in, const int* in_sizes, int n_in,
                              void* d_out, int out_size) {
    const float* x_indivi = (const float*)d_in[0];
    const float* x_src_a  = (const float*)d_in[1];
    const float* x_src_b  = (const float*)d_in[2];
    const int*   ei_a     = (const int*)d_in[3];
    const int*   ei_b     = (const int*)d_in[4];
    const float* ea_a     = (const float*)d_in[5];
    const float* ea_b     = (const float*)d_in[6];
    const float* wm_a     = (const float*)d_in[7];
    const float* bm_a     = (const float*)d_in[8];
    const float* root_a   = (const float*)d_in[9];
    const float* bias_a   = (const float*)d_in[10];
    const float* wm_b     = (const float*)d_in[11];
    const float* bm_b     = (const float*)d_in[12];
    const float* root_b   = (const float*)d_in[13];
    const float* bias_b   = (const float*)d_in[14];
    const float* w_lin    = (const float*)d_in[15];
    const float* b_lin    = (const float*)d_in[16];
    float* out = (float*)d_out;

    int N = in_sizes[0] / 16;
    int E = in_sizes[3] / 2;   // edge_index is [2, E]

    float* agg_base;
    __half* U_base;
    cudaGetSymbolAddress((void**)&agg_base, g_agg);
    cudaGetSymbolAddress((void**)&U_base, g_U);
    float* agg_a = agg_base;
    float* agg_b = agg_base + NMAX * 16;
    __half* U_a = U_base;
    __half* U_b = U_base + NMAX * UROW;

    dim3 pgrid((N + 127) / 128, 3);
    prep_kernel<<<pgrid, 128>>>(x_indivi, x_src_a, x_src_b,
                                root_a, bias_a, root_b, bias_b,
                                wm_a, bm_a, wm_b, bm_b, N);

    int eblocks = (E * 2 + 255) / 256;
    edge_kernel<<<eblocks, 256>>>(ei_a, ea_a, U_a, agg_a, E);
    edge_kernel<<<eblocks, 256>>>(ei_b, ea_b, U_b, agg_b, E);

    final_kernel<<<(N + 255) / 256, 256>>>(w_lin, b_lin, out, N);
}